// round 16
// baseline (speedup 1.0000x reference)
#include <cuda_runtime.h>
#include <cuda_fp16.h>
#include <cstdint>

typedef unsigned int u32;

// ---------------- problem constants ----------------
#define B_TOTAL 131072
#define T_SEQ   5
#define I_DIM   13
#define H_DIM   256
#define G_DIM   1024
#define OUT_DIM 6
#define XROW    (T_SEQ * I_DIM)      // 65

// ---------------- kernel config --------------------
#define TILE_M   64
#define THREADS  256
#define NCHUNKS  16
#define WCHUNK_H 17408               // halves per W chunk
#define WCHUNK_B 34816               // bytes per W chunk
#define NTG_B    4352                // bytes per ntg block within a chunk
#define HB       560                 // h row stride bytes
#define HSH      280                 // h row stride halves

// smem offsets (BYTES)
#define OFF_H    0                    // 64*560 = 35840
#define OFF_W    35840                // 2 x 34816 = 69632
#define OFF_BIAS 105472               // 4096
#define OFF_W1   109568               // 1536 halves = 3072 (per-t slice)
#define OFF_OUT  112640               // 1536
#define SMEM_BYTES 114176             // x2 CTAs = 228352 <= SM smem

// ---------------- device scratch -------------------
// W fragment-packed per chunk: [ntg 0..7]{ [s2 0..7][g][t4][16B s-pair], tail s=16 [g][t4][8B] }
__device__ __half g_W [NCHUNKS * WCHUNK_H];
// Wx compact: per chunk 1024 halves = [ntg 0..7][g 0..7][p 0..15]; 32 KB total
__device__ __half g_Wx[NCHUNKS * 1024];
__device__ float  g_bias[G_DIM];                   // interleaved n' = hu*4+gate
__device__ float  g_c[(size_t)H_DIM * B_TOTAL];    // c state [hu][b]

// ---------------- helpers --------------------------
__device__ __forceinline__ u32 smem_u32(const void* p) {
    u32 a;
    asm("{ .reg .u64 t; cvta.to.shared.u64 t, %1; cvt.u32.u64 %0, t; }"
        : "=r"(a) : "l"(p));
    return a;
}
__device__ __forceinline__ void cp_async16(u32 dst, const void* src) {
    asm volatile("cp.async.cg.shared.global [%0], [%1], 16;"
                 :: "r"(dst), "l"(src) : "memory");
}
#define CP_COMMIT() asm volatile("cp.async.commit_group;" ::: "memory")
#define CP_WAIT1()  asm volatile("cp.async.wait_group 1;" ::: "memory")

__device__ __forceinline__ void mma16(float& d0, float& d1, float& d2, float& d3,
                                      u32 a0, u32 a1, u32 a2, u32 a3,
                                      u32 b0, u32 b1) {
    asm volatile(
        "mma.sync.aligned.m16n8k16.row.col.f32.f16.f16.f32 "
        "{%0,%1,%2,%3}, {%4,%5,%6,%7}, {%8,%9}, {%0,%1,%2,%3};"
        : "+f"(d0), "+f"(d1), "+f"(d2), "+f"(d3)
        : "r"(a0), "r"(a1), "r"(a2), "r"(a3), "r"(b0), "r"(b1));
}
__device__ __forceinline__ float tanh_a(float x) {
    float r; asm("tanh.approx.f32 %0, %1;" : "=f"(r) : "f"(x)); return r;
}
__device__ __forceinline__ float sigmoid_a(float x) {
    return fmaf(tanh_a(0.5f * x), 0.5f, 0.5f);
}
__device__ __forceinline__ int pos16(int kk) {
    int j = kk >> 1, b = kk & 1;
    int slot = ((j & 3) << 1) | (j >> 2);
    return slot * 2 + b;
}
__device__ __forceinline__ void epi_block(const float* d4, bool even,
                                          const float* bias_s, int nb,
                                          float cold, float& cn, float& hv) {
    const float sx = even ? d4[2] : d4[0];
    const float sy = even ? d4[3] : d4[1];
    const float rx = __shfl_xor_sync(0xFFFFFFFFu, sx, 1);
    const float ry = __shfl_xor_sync(0xFFFFFFFFu, sy, 1);
    const float vi = even ? d4[0] : rx;
    const float vf = even ? d4[1] : ry;
    const float vg = even ? rx : d4[2];
    const float vo = even ? ry : d4[3];
    const float i_ = sigmoid_a(vi + bias_s[nb + 0]);
    const float f_ = sigmoid_a(vf + bias_s[nb + 1]);
    const float g_ = tanh_a   (vg + bias_s[nb + 2]);
    const float o_ = sigmoid_a(vo + bias_s[nb + 3]);
    cn = fmaf(f_, cold, i_ * g_);
    hv = o_ * tanh_a(cn);
}

// ---------------- prep kernel (layouts proven in R13/R15) ----------------
__global__ void prep_kernel(const float* __restrict__ W_ih,
                            const float* __restrict__ W_hh,
                            const float* __restrict__ b_ih,
                            const float* __restrict__ b_hh) {
    int idx = blockIdx.x * blockDim.x + threadIdx.x;
    int stride = gridDim.x * blockDim.x;
    const int TOT1 = NCHUNKS * WCHUNK_H;
    for (int e = idx; e < TOT1; e += stride) {
        int chunk = e / WCHUNK_H;
        int r1 = e % WCHUNK_H;
        int ntg = r1 / 2176;
        int inner = r1 % 2176;
        int s, p, g;
        if (inner < 2048) {
            int s2 = inner >> 8;
            int r = inner & 255;
            g = r >> 5;
            int r2 = r & 31;
            int t4 = r2 >> 3;
            int r3 = r2 & 7;
            s = s2 * 2 + (r3 >> 2);
            p = t4 * 4 + (r3 & 3);
        } else {
            int i2 = inner - 2048;
            g = i2 >> 4; p = i2 & 15; s = 16;
        }
        int slot = p >> 1, b = p & 1;
        int j = (slot >> 1) | ((slot & 1) << 2);
        int k = s * 16 + j * 2 + b;
        int col = chunk * 64 + ntg * 8 + g;
        int hu = col >> 2, gate = col & 3;
        int r = gate * H_DIM + hu;
        float v = 0.0f;
        if (k < H_DIM)              v = W_hh[r * H_DIM + k];
        else if (k < H_DIM + I_DIM) v = W_ih[r * I_DIM + (k - H_DIM)];
        g_W[e] = __float2half(v);
    }
    const int TOT2 = NCHUNKS * 1024;
    for (int e = idx; e < TOT2; e += stride) {
        int chunk = e >> 10;
        int i2 = e & 1023;
        int ntg = i2 >> 7;
        int r0 = i2 & 127;
        int g = r0 >> 4, p = r0 & 15;
        int slot = p >> 1, b = p & 1;
        int j = (slot >> 1) | ((slot & 1) << 2);
        int k = 256 + j * 2 + b;
        int col = chunk * 64 + ntg * 8 + g;
        int hu = col >> 2, gate = col & 3;
        int r = gate * H_DIM + hu;
        float v = 0.0f;
        if (k < H_DIM + I_DIM) v = W_ih[r * I_DIM + (k - H_DIM)];
        g_Wx[e] = __float2half(v);
    }
    for (int e = idx; e < G_DIM; e += stride) {
        int hu = e >> 2, gate = e & 3;
        g_bias[e] = b_ih[gate * H_DIM + hu] + b_hh[gate * H_DIM + hu];
    }
}

// ---------------- main fused kernel ----------------
__global__ __launch_bounds__(THREADS, 2)
void lstm_kernel(const float* __restrict__ x,
                 const float* __restrict__ W1,
                 const float* __restrict__ b1,
                 float* __restrict__ out) {
    extern __shared__ char smc[];
    const u32 sb   = smem_u32(smc);
    __half* hsm    = (__half*)(smc + OFF_H);
    float*  bias_s = (float*)(smc + OFF_BIAS);
    __half* w1s    = (__half*)(smc + OFF_W1);
    float*  out_s  = (float*)(smc + OFF_OUT);

    const int tid = threadIdx.x;
    const int b0  = blockIdx.x * TILE_M;

    const int wid  = tid >> 5;
    const int lane = tid & 31;
    const int g    = lane >> 2;
    const int t4   = lane & 3;
    const int rt   = wid >> 1;       // row tile (16 rows)
    const int nh   = wid & 1;        // n half (4 ntg)
    const int r0   = rt * 16;
    const int rpar = (t4 & 1) * 8;
    const int hu_sel = t4 >> 1;
    const bool even  = ((t4 & 1) == 0);
    const int myrow  = r0 + g + rpar;

    // epilogue address precompute (per-warp invariants)
    int hw_off[4];                   // h-write lane offset within 16-col block
    #pragma unroll
    for (int nt = 0; nt < 4; nt++)
        hw_off[nt] = myrow * HSH + pos16(((nh * 4 + nt) * 2 + hu_sel) & 15);
    const int hu0 = (nh * 4) * 2 + hu_sel;   // hu for c=0, nt=0 (step 2 per nt)

    // ---- one-time staging ----
    for (int e = tid; e < G_DIM; e += THREADS) bias_s[e] = g_bias[e];
    for (int e = tid; e < TILE_M * OUT_DIM; e += THREADS) out_s[e] = 0.0f;
    for (int e = tid; e < TILE_M * 16; e += THREADS) {         // x(t=0)
        int row = e >> 4, i = e & 15;
        float v = (i < I_DIM) ? x[(size_t)(b0 + row) * XROW + i] : 0.0f;
        hsm[row * HSH + 256 + pos16(i)] = __float2half(v);
    }
    for (int e = tid; e < OUT_DIM * H_DIM; e += THREADS)       // W1 slice t=0
        w1s[e] = __float2half(W1[(e >> 8) * (T_SEQ * H_DIM) + (e & 255)]);

    // ---- prologue: Wx -> buf0, chunk0 -> buf1 ----
    {
        const u32 dst = sb + OFF_W;
        #pragma unroll
        for (int i = 0; i < 8; i++) {
            int e = tid + i * THREADS;   // 2048 16B slots = 32 KB = all of g_Wx
            cp_async16(dst + (u32)e * 16, (const char*)g_Wx + (size_t)e * 16);
        }
        CP_COMMIT();
    }
    {
        const u32 dst = sb + OFF_W + WCHUNK_B;
        #pragma unroll
        for (int i = 0; i < 9; i++) {
            int e = tid + i * THREADS;
            if (e < WCHUNK_B / 16)
                cp_async16(dst + (u32)e * 16, (const char*)g_W + (size_t)e * 16);
        }
        CP_COMMIT();
    }
    CP_WAIT1();          // Wx landed (chunk0 may pend)
    __syncthreads();

    float oacc[OUT_DIM];
    #pragma unroll
    for (int o = 0; o < OUT_DIM; o++) oacc[o] = 0.0f;

    const char* ap = smc + OFF_H + (size_t)(r0 + g) * HB + t4 * 8;

    // ================= t = 0 (x-only; Wx resident in buf0; no syncs) =========
    {
        const uint2 x0L = *(const uint2*)(ap + 512);
        const uint2 x0H = *(const uint2*)(ap + 8 * HB + 512);
        #pragma unroll 1
        for (int c = 0; c < NCHUNKS; c++) {
            float d[4][4];
            #pragma unroll
            for (int nt = 0; nt < 4; nt++)
                #pragma unroll
                for (int q = 0; q < 4; q++) d[nt][q] = 0.0f;
            #pragma unroll
            for (int nt = 0; nt < 4; nt++) {
                const uint2 bx = *(const uint2*)(smc + OFF_W + c * 2048
                                    + (nh * 4 + nt) * 256 + g * 32 + t4 * 8);
                mma16(d[nt][0], d[nt][1], d[nt][2], d[nt][3],
                      x0L.x, x0H.x, x0L.y, x0H.y, bx.x, bx.y);
            }
            #pragma unroll
            for (int nt = 0; nt < 4; nt++) {
                const int hu = c * 16 + hu0 + nt * 2;
                const int nb = c * 64 + (nh * 4 + nt) * 8 + hu_sel * 4;
                float cn, hv;
                epi_block(d[nt], even, bias_s, nb, 0.0f, cn, hv);
                g_c[(size_t)hu * B_TOTAL + b0 + myrow] = cn;
                hsm[c * 16 + hw_off[nt]] = __float2half(hv);
                #pragma unroll
                for (int o = 0; o < OUT_DIM; o++)
                    oacc[o] = fmaf(hv, __half2float(w1s[o * H_DIM + hu]), oacc[o]);
            }
        }
    }

    // ================= t = 1..4 =================
    #pragma unroll 1
    for (int t = 1; t < T_SEQ; t++) {
        const bool last = (t == T_SEQ - 1);
        __syncthreads();   // all prior-t epilogues done (w1s readers, h writers)
        // stage x_t + W1 slice
        for (int e = tid; e < TILE_M * 16; e += THREADS) {
            int row = e >> 4, i = e & 15;
            float v = (i < I_DIM)
                ? x[(size_t)(b0 + row) * XROW + t * I_DIM + i] : 0.0f;
            hsm[row * HSH + 256 + pos16(i)] = __float2half(v);
        }
        for (int e = tid; e < OUT_DIM * H_DIM; e += THREADS)
            w1s[e] = __float2half(
                W1[(e >> 8) * (T_SEQ * H_DIM) + t * H_DIM + (e & 255)]);
        __syncthreads();   // staging visible to all warps

        // A fragments once per t
        uint2 aL[17], aH[17];
        #pragma unroll
        for (int s = 0; s < 17; s++) {
            aL[s] = *(const uint2*)(ap + s * 32);
            aH[s] = *(const uint2*)(ap + 8 * HB + s * 32);
        }

        #pragma unroll 1
        for (int c = 0; c < NCHUNKS; c++) {
            const int giter = (t - 1) * NCHUNKS + c;
            const int buf   = 1 - (giter & 1);      // chunk0 -> buf1

            // prefetch chunk giter+1 into buf giter&1 (freed by pre-epilogue sync)
            if (giter < T_SEQ * NCHUNKS - NCHUNKS - 1) {
                const int nc = (giter + 1) & (NCHUNKS - 1);
                const char* src = (const char*)(g_W + (size_t)nc * WCHUNK_H);
                const u32 dst = sb + OFF_W + (u32)(giter & 1) * WCHUNK_B;
                #pragma unroll
                for (int i = 0; i < 9; i++) {
                    int e = tid + i * THREADS;
                    if (e < WCHUNK_B / 16)
                        cp_async16(dst + (u32)e * 16, src + (size_t)e * 16);
                }
            }
            CP_COMMIT();
            CP_WAIT1();          // current chunk landed

            // c-state prefetch (per-warp private; no cross-warp dependency)
            float cold[4];
            #pragma unroll
            for (int nt = 0; nt < 4; nt++) {
                const int hu = c * 16 + hu0 + nt * 2;
                cold[nt] = g_c[(size_t)hu * B_TOTAL + b0 + myrow];
            }

            // ---- MMA: LDS.128 B loads ----
            float d[4][4];
            #pragma unroll
            for (int nt = 0; nt < 4; nt++)
                #pragma unroll
                for (int q = 0; q < 4; q++) d[nt][q] = 0.0f;

            const char* wb = smc + OFF_W + buf * WCHUNK_B
                             + (nh * 4) * NTG_B + g * 64 + t4 * 16;
            #pragma unroll
            for (int s2 = 0; s2 < 8; s2++) {
                #pragma unroll
                for (int nt = 0; nt < 4; nt++) {
                    const uint4 q = *(const uint4*)(wb + nt * NTG_B + s2 * 512);
                    mma16(d[nt][0], d[nt][1], d[nt][2], d[nt][3],
                          aL[2*s2].x, aH[2*s2].x, aL[2*s2].y, aH[2*s2].y,
                          q.x, q.y);
                    mma16(d[nt][0], d[nt][1], d[nt][2], d[nt][3],
                          aL[2*s2+1].x, aH[2*s2+1].x, aL[2*s2+1].y, aH[2*s2+1].y,
                          q.z, q.w);
                }
            }
            {   // tail s = 16 (x block)
                const char* wt = smc + OFF_W + buf * WCHUNK_B
                                 + (nh * 4) * NTG_B + 4096 + g * 32 + t4 * 8;
                #pragma unroll
                for (int nt = 0; nt < 4; nt++) {
                    const uint2 q = *(const uint2*)(wt + nt * NTG_B);
                    mma16(d[nt][0], d[nt][1], d[nt][2], d[nt][3],
                          aL[16].x, aH[16].x, aL[16].y, aH[16].y, q.x, q.y);
                }
            }

            // ---- BARRIER BEFORE EPILOGUE: all B reads done -> buffer free.
            // Epilogue below overlaps other warps' next-chunk prefetch + MMAs.
            __syncthreads();

            // ---- epilogue (no W-buffer access; cross-warp safe) ----
            #pragma unroll
            for (int nt = 0; nt < 4; nt++) {
                const int hu = c * 16 + hu0 + nt * 2;
                const int nb = c * 64 + (nh * 4 + nt) * 8 + hu_sel * 4;
                float cn, hv;
                epi_block(d[nt], even, bias_s, nb, cold[nt], cn, hv);
                if (!last) {
                    g_c[(size_t)hu * B_TOTAL + b0 + myrow] = cn;
                    hsm[c * 16 + hw_off[nt]] = __float2half(hv);
                }
                #pragma unroll
                for (int o = 0; o < OUT_DIM; o++)
                    oacc[o] = fmaf(hv, __half2float(w1s[o * H_DIM + hu]), oacc[o]);
            }
        }
    }

    // ---- reduce head partials and write out ----
    __syncthreads();     // out_s zero-init + all epilogues ordered
    #pragma unroll
    for (int o = 0; o < OUT_DIM; o++)
        atomicAdd(&out_s[myrow * OUT_DIM + o], oacc[o]);
    __syncthreads();
    for (int e = tid; e < TILE_M * OUT_DIM; e += THREADS) {
        const int row = e / OUT_DIM, o = e % OUT_DIM;
        out[(size_t)(b0 + row) * OUT_DIM + o] = out_s[e] + b1[o];
    }
}

// ---------------------------------------------------------------------------
extern "C" void kernel_launch(void* const* d_in, const int* in_sizes, int n_in,
                              void* d_out, int out_size) {
    const float* x    = (const float*)d_in[0];
    const float* W_ih = (const float*)d_in[1];
    const float* W_hh = (const float*)d_in[2];
    const float* b_ih = (const float*)d_in[3];
    const float* b_hh = (const float*)d_in[4];
    const float* W1   = (const float*)d_in[5];
    const float* b1   = (const float*)d_in[6];
    float* out = (float*)d_out;

    cudaFuncSetAttribute(lstm_kernel,
                         cudaFuncAttributeMaxDynamicSharedMemorySize, SMEM_BYTES);

    prep_kernel<<<288, 256>>>(W_ih, W_hh, b_ih, b_hh);
    lstm_kernel<<<B_TOTAL / TILE_M, THREADS, SMEM_BYTES>>>(x, W1, b1, out);
}

// round 17
// speedup vs baseline: 1.1141x; 1.1141x over previous
#include <cuda_runtime.h>
#include <cuda_fp16.h>
#include <cstdint>

typedef unsigned int u32;

// ---------------- problem constants ----------------
#define B_TOTAL 131072
#define T_SEQ   5
#define I_DIM   13
#define H_DIM   256
#define G_DIM   1024
#define OUT_DIM 6
#define XROW    (T_SEQ * I_DIM)      // 65

// ---------------- kernel config --------------------
#define TILE_M   64
#define THREADS  256
#define NCHUNKS  16
#define WCHUNK_H 17408               // halves per W chunk
#define WCHUNK_B 34816               // bytes per W chunk
#define NTG_B    4352                // bytes per ntg block within a chunk
#define HB       560                 // h row stride bytes
#define HSH      280                 // h row stride halves

// smem offsets (BYTES)
#define OFF_H    0                    // 64*560 = 35840
#define OFF_W    35840                // 2 x 34816 = 69632
#define OFF_BIAS 105472               // 4096
#define OFF_W1   109568               // 256 hu x 8 halves = 4096 (t-slice, [hu][8])
#define OFF_OUT  113664               // 1536
#define SMEM_BYTES 115200             // x2 CTAs = 230400 <= 233472

// ---------------- device scratch -------------------
// W fragment-packed per chunk: [ntg 0..7]{ [s2 0..7][g][t4][16B s-pair], tail s=16 [g][t4][8B] }
__device__ __half g_W [NCHUNKS * WCHUNK_H];
// Wx compact: per chunk 1024 halves = [ntg 0..7][g 0..7][p 0..15]; 32 KB total
__device__ __half g_Wx[NCHUNKS * 1024];
__device__ float  g_bias[G_DIM];                   // interleaved n' = hu*4+gate
__device__ float  g_c[(size_t)H_DIM * B_TOTAL];    // c state [hu][b]

// ---------------- helpers --------------------------
__device__ __forceinline__ u32 smem_u32(const void* p) {
    u32 a;
    asm("{ .reg .u64 t; cvta.to.shared.u64 t, %1; cvt.u32.u64 %0, t; }"
        : "=r"(a) : "l"(p));
    return a;
}
__device__ __forceinline__ void cp_async16(u32 dst, const void* src) {
    asm volatile("cp.async.cg.shared.global [%0], [%1], 16;"
                 :: "r"(dst), "l"(src) : "memory");
}
#define CP_COMMIT() asm volatile("cp.async.commit_group;" ::: "memory")
#define CP_WAIT1()  asm volatile("cp.async.wait_group 1;" ::: "memory")

__device__ __forceinline__ void mma16(float& d0, float& d1, float& d2, float& d3,
                                      u32 a0, u32 a1, u32 a2, u32 a3,
                                      u32 b0, u32 b1) {
    asm volatile(
        "mma.sync.aligned.m16n8k16.row.col.f32.f16.f16.f32 "
        "{%0,%1,%2,%3}, {%4,%5,%6,%7}, {%8,%9}, {%0,%1,%2,%3};"
        : "+f"(d0), "+f"(d1), "+f"(d2), "+f"(d3)
        : "r"(a0), "r"(a1), "r"(a2), "r"(a3), "r"(b0), "r"(b1));
}
__device__ __forceinline__ float tanh_a(float x) {
    float r; asm("tanh.approx.f32 %0, %1;" : "=f"(r) : "f"(x)); return r;
}
__device__ __forceinline__ float sigmoid_a(float x) {
    return fmaf(tanh_a(0.5f * x), 0.5f, 0.5f);
}
__device__ __forceinline__ int pos16(int kk) {
    int j = kk >> 1, b = kk & 1;
    int slot = ((j & 3) << 1) | (j >> 2);
    return slot * 2 + b;
}
// gate exchange + cell update; bias passed as a prefetched float4
__device__ __forceinline__ void epi_block(const float* d4, bool even,
                                          float4 b4,
                                          float cold, float& cn, float& hv) {
    const float sx = even ? d4[2] : d4[0];
    const float sy = even ? d4[3] : d4[1];
    const float rx = __shfl_xor_sync(0xFFFFFFFFu, sx, 1);
    const float ry = __shfl_xor_sync(0xFFFFFFFFu, sy, 1);
    const float vi = even ? d4[0] : rx;
    const float vf = even ? d4[1] : ry;
    const float vg = even ? rx : d4[2];
    const float vo = even ? ry : d4[3];
    const float i_ = sigmoid_a(vi + b4.x);
    const float f_ = sigmoid_a(vf + b4.y);
    const float g_ = tanh_a   (vg + b4.z);
    const float o_ = sigmoid_a(vo + b4.w);
    cn = fmaf(f_, cold, i_ * g_);
    hv = o_ * tanh_a(cn);
}
// head accumulate: one LDS.128 of [hu][8] halves -> 6 fmaf
__device__ __forceinline__ void head_acc(const __half* w1s, int hu, float hv,
                                         float* oacc) {
    const uint4 wq = *(const uint4*)((const char*)w1s + hu * 16);
    const float2 f0 = __half22float2(*(const __half2*)&wq.x);
    const float2 f1 = __half22float2(*(const __half2*)&wq.y);
    const float2 f2 = __half22float2(*(const __half2*)&wq.z);
    oacc[0] = fmaf(hv, f0.x, oacc[0]);
    oacc[1] = fmaf(hv, f0.y, oacc[1]);
    oacc[2] = fmaf(hv, f1.x, oacc[2]);
    oacc[3] = fmaf(hv, f1.y, oacc[3]);
    oacc[4] = fmaf(hv, f2.x, oacc[4]);
    oacc[5] = fmaf(hv, f2.y, oacc[5]);
}

// ---------------- prep kernel (layouts proven R13/R15) ----------------
__global__ void prep_kernel(const float* __restrict__ W_ih,
                            const float* __restrict__ W_hh,
                            const float* __restrict__ b_ih,
                            const float* __restrict__ b_hh) {
    int idx = blockIdx.x * blockDim.x + threadIdx.x;
    int stride = gridDim.x * blockDim.x;
    const int TOT1 = NCHUNKS * WCHUNK_H;
    for (int e = idx; e < TOT1; e += stride) {
        int chunk = e / WCHUNK_H;
        int r1 = e % WCHUNK_H;
        int ntg = r1 / 2176;
        int inner = r1 % 2176;
        int s, p, g;
        if (inner < 2048) {
            int s2 = inner >> 8;
            int r = inner & 255;
            g = r >> 5;
            int r2 = r & 31;
            int t4 = r2 >> 3;
            int r3 = r2 & 7;
            s = s2 * 2 + (r3 >> 2);
            p = t4 * 4 + (r3 & 3);
        } else {
            int i2 = inner - 2048;
            g = i2 >> 4; p = i2 & 15; s = 16;
        }
        int slot = p >> 1, b = p & 1;
        int j = (slot >> 1) | ((slot & 1) << 2);
        int k = s * 16 + j * 2 + b;
        int col = chunk * 64 + ntg * 8 + g;
        int hu = col >> 2, gate = col & 3;
        int r = gate * H_DIM + hu;
        float v = 0.0f;
        if (k < H_DIM)              v = W_hh[r * H_DIM + k];
        else if (k < H_DIM + I_DIM) v = W_ih[r * I_DIM + (k - H_DIM)];
        g_W[e] = __float2half(v);
    }
    const int TOT2 = NCHUNKS * 1024;
    for (int e = idx; e < TOT2; e += stride) {
        int chunk = e >> 10;
        int i2 = e & 1023;
        int ntg = i2 >> 7;
        int r0 = i2 & 127;
        int g = r0 >> 4, p = r0 & 15;
        int slot = p >> 1, b = p & 1;
        int j = (slot >> 1) | ((slot & 1) << 2);
        int k = 256 + j * 2 + b;
        int col = chunk * 64 + ntg * 8 + g;
        int hu = col >> 2, gate = col & 3;
        int r = gate * H_DIM + hu;
        float v = 0.0f;
        if (k < H_DIM + I_DIM) v = W_ih[r * I_DIM + (k - H_DIM)];
        g_Wx[e] = __float2half(v);
    }
    for (int e = idx; e < G_DIM; e += stride) {
        int hu = e >> 2, gate = e & 3;
        g_bias[e] = b_ih[gate * H_DIM + hu] + b_hh[gate * H_DIM + hu];
    }
}

// ---------------- main fused kernel ----------------
__global__ __launch_bounds__(THREADS, 2)
void lstm_kernel(const float* __restrict__ x,
                 const float* __restrict__ W1,
                 const float* __restrict__ b1,
                 float* __restrict__ out) {
    extern __shared__ char smc[];
    const u32 sb   = smem_u32(smc);
    __half* hsm    = (__half*)(smc + OFF_H);
    float*  bias_s = (float*)(smc + OFF_BIAS);
    __half* w1s    = (__half*)(smc + OFF_W1);
    float*  out_s  = (float*)(smc + OFF_OUT);

    const int tid = threadIdx.x;
    const int b0  = blockIdx.x * TILE_M;

    const int wid  = tid >> 5;
    const int lane = tid & 31;
    const int g    = lane >> 2;
    const int t4   = lane & 3;
    const int rt   = wid >> 1;       // row tile (16 rows)
    const int nh   = wid & 1;        // n half (4 ntg)
    const int r0   = rt * 16;
    const int rpar = (t4 & 1) * 8;
    const int hu_sel = t4 >> 1;
    const bool even  = ((t4 & 1) == 0);
    const int myrow  = r0 + g + rpar;

    // ---- one-time staging ----
    for (int e = tid; e < G_DIM; e += THREADS) bias_s[e] = g_bias[e];
    for (int e = tid; e < TILE_M * OUT_DIM; e += THREADS) out_s[e] = 0.0f;
    for (int e = tid; e < TILE_M * 16; e += THREADS) {         // x(t=0)
        int row = e >> 4, i = e & 15;
        float v = (i < I_DIM) ? x[(size_t)(b0 + row) * XROW + i] : 0.0f;
        hsm[row * HSH + 256 + pos16(i)] = __float2half(v);
    }
    for (int e = tid; e < H_DIM * 8; e += THREADS) {           // W1 t=0, [hu][8]
        int hu = e >> 3, o = e & 7;
        float v = (o < OUT_DIM) ? W1[o * (T_SEQ * H_DIM) + hu] : 0.0f;
        w1s[e] = __float2half(v);
    }

    // ---- prologue: Wx -> buf0, chunk0 -> buf1 ----
    {
        const u32 dst = sb + OFF_W;
        #pragma unroll
        for (int i = 0; i < 8; i++) {
            int e = tid + i * THREADS;
            cp_async16(dst + (u32)e * 16, (const char*)g_Wx + (size_t)e * 16);
        }
        CP_COMMIT();
    }
    {
        const u32 dst = sb + OFF_W + WCHUNK_B;
        #pragma unroll
        for (int i = 0; i < 9; i++) {
            int e = tid + i * THREADS;
            if (e < WCHUNK_B / 16)
                cp_async16(dst + (u32)e * 16, (const char*)g_W + (size_t)e * 16);
        }
        CP_COMMIT();
    }
    CP_WAIT1();          // Wx landed (chunk0 may pend)
    __syncthreads();

    float oacc[OUT_DIM];
    #pragma unroll
    for (int o = 0; o < OUT_DIM; o++) oacc[o] = 0.0f;

    const char* ap = smc + OFF_H + (size_t)(r0 + g) * HB + t4 * 8;
    const int hu0 = (nh * 4) * 2 + hu_sel;   // hu at nt=0 (step 2 per nt)

    // ================= t = 0 (x-only; Wx resident in buf0; no syncs) =========
    {
        const uint2 x0L = *(const uint2*)(ap + 512);
        const uint2 x0H = *(const uint2*)(ap + 8 * HB + 512);
        #pragma unroll 1
        for (int c = 0; c < NCHUNKS; c++) {
            float d[4][4];
            #pragma unroll
            for (int nt = 0; nt < 4; nt++)
                #pragma unroll
                for (int q = 0; q < 4; q++) d[nt][q] = 0.0f;
            #pragma unroll
            for (int nt = 0; nt < 4; nt++) {
                const uint2 bx = *(const uint2*)(smc + OFF_W + c * 2048
                                    + (nh * 4 + nt) * 256 + g * 32 + t4 * 8);
                mma16(d[nt][0], d[nt][1], d[nt][2], d[nt][3],
                      x0L.x, x0H.x, x0L.y, x0H.y, bx.x, bx.y);
            }
            #pragma unroll
            for (int nt = 0; nt < 4; nt++) {
                const int hu = c * 16 + hu0 + nt * 2;
                const float4 b4 = *(const float4*)(bias_s + c * 64
                                     + (nh * 4 + nt) * 8 + hu_sel * 4);
                float cn, hv;
                epi_block(d[nt], even, b4, 0.0f, cn, hv);
                g_c[(size_t)hu * B_TOTAL + b0 + myrow] = cn;
                hsm[myrow * HSH + (hu >> 4) * 16 + pos16(hu & 15)] = __float2half(hv);
                head_acc(w1s, hu, hv, oacc);
            }
        }
    }
    __syncthreads();     // buf0 (Wx) free; all t=0 h writes complete

    // ================= t = 1..4 =================
    #pragma unroll 1
    for (int t = 1; t < T_SEQ; t++) {
        const bool last = (t == T_SEQ - 1);
        // stage x_t + W1 slice (ordered by trailing chunk-15 sync / t=0 sync)
        for (int e = tid; e < TILE_M * 16; e += THREADS) {
            int row = e >> 4, i = e & 15;
            float v = (i < I_DIM)
                ? x[(size_t)(b0 + row) * XROW + t * I_DIM + i] : 0.0f;
            hsm[row * HSH + 256 + pos16(i)] = __float2half(v);
        }
        for (int e = tid; e < H_DIM * 8; e += THREADS) {
            int hu = e >> 3, o = e & 7;
            float v = (o < OUT_DIM)
                ? W1[o * (T_SEQ * H_DIM) + t * H_DIM + hu] : 0.0f;
            w1s[e] = __float2half(v);
        }

        uint2 aL[17], aH[17];

        #pragma unroll 1
        for (int c = 0; c < NCHUNKS; c++) {
            const int giter = (t - 1) * NCHUNKS + c;
            const int buf   = 1 - (giter & 1);      // chunk0 -> buf1

            // prefetch chunk giter+1 into buf giter&1 (freed by trailing sync)
            if (giter < T_SEQ * NCHUNKS - NCHUNKS - 1) {
                const int nc = (giter + 1) & (NCHUNKS - 1);
                const char* src = (const char*)(g_W + (size_t)nc * WCHUNK_H);
                const u32 dst = sb + OFF_W + (u32)(giter & 1) * WCHUNK_B;
                #pragma unroll
                for (int i = 0; i < 9; i++) {
                    int e = tid + i * THREADS;
                    if (e < WCHUNK_B / 16)
                        cp_async16(dst + (u32)e * 16, src + (size_t)e * 16);
                }
            }
            CP_COMMIT();
            CP_WAIT1();          // current chunk landed
            __syncthreads();     // staging/h/frag visibility

            if (c == 0) {        // A fragments once per t
                #pragma unroll
                for (int s = 0; s < 17; s++) {
                    aL[s] = *(const uint2*)(ap + s * 32);
                    aH[s] = *(const uint2*)(ap + 8 * HB + s * 32);
                }
            }

            // c-state prefetch
            float cold[4];
            #pragma unroll
            for (int nt = 0; nt < 4; nt++) {
                const int hu = c * 16 + hu0 + nt * 2;
                cold[nt] = g_c[(size_t)hu * B_TOTAL + b0 + myrow];
            }

            // ---- MMA: LDS.128 B loads ----
            float d[4][4];
            #pragma unroll
            for (int nt = 0; nt < 4; nt++)
                #pragma unroll
                for (int q = 0; q < 4; q++) d[nt][q] = 0.0f;

            const char* wb = smc + OFF_W + buf * WCHUNK_B
                             + (nh * 4) * NTG_B + g * 64 + t4 * 16;
            #pragma unroll
            for (int s2 = 0; s2 < 8; s2++) {
                #pragma unroll
                for (int nt = 0; nt < 4; nt++) {
                    const uint4 q = *(const uint4*)(wb + nt * NTG_B + s2 * 512);
                    mma16(d[nt][0], d[nt][1], d[nt][2], d[nt][3],
                          aL[2*s2].x, aH[2*s2].x, aL[2*s2].y, aH[2*s2].y,
                          q.x, q.y);
                    mma16(d[nt][0], d[nt][1], d[nt][2], d[nt][3],
                          aL[2*s2+1].x, aH[2*s2+1].x, aL[2*s2+1].y, aH[2*s2+1].y,
                          q.z, q.w);
                }
            }
            {   // tail s = 16 (x block)
                const char* wt = smc + OFF_W + buf * WCHUNK_B
                                 + (nh * 4) * NTG_B + 4096 + g * 32 + t4 * 8;
                #pragma unroll
                for (int nt = 0; nt < 4; nt++) {
                    const uint2 q = *(const uint2*)(wt + nt * NTG_B);
                    mma16(d[nt][0], d[nt][1], d[nt][2], d[nt][3],
                          aL[16].x, aH[16].x, aL[16].y, aH[16].y, q.x, q.y);
                }
            }

            // ---- epilogue (vectorized operand loads) ----
            #pragma unroll
            for (int nt = 0; nt < 4; nt++) {
                const int hu = c * 16 + hu0 + nt * 2;
                const float4 b4 = *(const float4*)(bias_s + c * 64
                                     + (nh * 4 + nt) * 8 + hu_sel * 4);
                float cn, hv;
                epi_block(d[nt], even, b4, cold[nt], cn, hv);
                if (!last) {
                    g_c[(size_t)hu * B_TOTAL + b0 + myrow] = cn;
                    hsm[myrow * HSH + (hu >> 4) * 16 + pos16(hu & 15)] =
                        __float2half(hv);
                }
                head_acc(w1s, hu, hv, oacc);
            }
            __syncthreads();   // release buf for the next prefetch (R15 position)
        }
    }

    // ---- reduce head partials and write out ----
    #pragma unroll
    for (int o = 0; o < OUT_DIM; o++)
        atomicAdd(&out_s[myrow * OUT_DIM + o], oacc[o]);
    __syncthreads();
    for (int e = tid; e < TILE_M * OUT_DIM; e += THREADS) {
        const int row = e / OUT_DIM, o = e % OUT_DIM;
        out[(size_t)(b0 + row) * OUT_DIM + o] = out_s[e] + b1[o];
    }
}

// ---------------------------------------------------------------------------
extern "C" void kernel_launch(void* const* d_in, const int* in_sizes, int n_in,
                              void* d_out, int out_size) {
    const float* x    = (const float*)d_in[0];
    const float* W_ih = (const float*)d_in[1];
    const float* W_hh = (const float*)d_in[2];
    const float* b_ih = (const float*)d_in[3];
    const float* b_hh = (const float*)d_in[4];
    const float* W1   = (const float*)d_in[5];
    const float* b1   = (const float*)d_in[6];
    float* out = (float*)d_out;

    cudaFuncSetAttribute(lstm_kernel,
                         cudaFuncAttributeMaxDynamicSharedMemorySize, SMEM_BYTES);

    prep_kernel<<<288, 256>>>(W_ih, W_hh, b_ih, b_hh);
    lstm_kernel<<<B_TOTAL / TILE_M, THREADS, SMEM_BYTES>>>(x, W1, b1, out);
}